// round 16
// baseline (speedup 1.0000x reference)
#include <cuda_runtime.h>
#include <math.h>
#include <float.h>

#define N 256
#define NBLK 128              // 2 rows per block, single wave
#define FULL 0xffffffffu

typedef unsigned long long ull;

// packed f32x2 fused multiply-add: acc.lo += a.lo*b.lo; acc.hi += a.hi*b.hi
#define FMA2(acc, a, b) \
    asm("fma.rn.f32x2 %0, %1, %2, %3;" : "=l"(acc) : "l"(a), "l"(b), "l"(acc))

__device__ __forceinline__ float unpack_add(ull v) {
    float lo, hi;
    asm("mov.b64 {%0,%1}, %2;" : "=f"(lo), "=f"(hi) : "l"(v));
    return lo + hi;
}

__device__ float2 g_part[NBLK];
__device__ unsigned int g_ticket = 0;   // reset by last block each launch

// Dynamic smem: sE = full E (8192 float4, swizzled: row j chunk c at j*32+((c+j)&31)),
// then sA = per-warp private anchor copies (8 warps * 2 rows * 32 chunks).
extern __shared__ float4 sE[];

__global__ void __launch_bounds__(256, 1)
triplet_fused(const float* __restrict__ emb,
              const int*   __restrict__ lab32,
              float*       __restrict__ out) {
    __shared__ float  Dmat[2 * N];
    __shared__ float  negd[2 * N];
    __shared__ unsigned short pairs[2 * N];
    __shared__ int    cnts[16];
    __shared__ float  wsum[8];

    const int t = threadIdx.x;
    const int b = blockIdx.x;
    const int w = t >> 5, l = t & 31;
    const int i0 = b * 2, i1 = i0 + 1;
    float4* sA = sE + 8192 + w * 64;     // this warp's anchor slot

    // ---- Per-warp staging: anchors first (uniform, L2-broadcast), then own rows.
    const float4* E4 = reinterpret_cast<const float4*>(emb);
    const float4 a0c = E4[i0 * 32 + l];  // chunk l of anchor 0
    const float4 a1c = E4[i1 * 32 + l];  // chunk l of anchor 1
    sA[l]      = a0c;
    sA[32 + l] = a1c;
    const int jbase = w * 32;
#pragma unroll
    for (int jj = 0; jj < 32; ++jj) {
        const int j = jbase + jj;
        sE[(j << 5) + ((l + j) & 31)] = E4[j * 32 + l];   // swizzled, conflict-free
    }

    // ---- Anchor norms via shfl butterfly (overlaps staging LDG latency).
    float pn0 = a0c.x*a0c.x + a0c.y*a0c.y + a0c.z*a0c.z + a0c.w*a0c.w;
    float pn1 = a1c.x*a1c.x + a1c.y*a1c.y + a1c.z*a1c.z + a1c.w*a1c.w;
#pragma unroll
    for (int s = 16; s > 0; s >>= 1) {
        pn0 += __shfl_xor_sync(FULL, pn0, s);
        pn1 += __shfl_xor_sync(FULL, pn1, s);
    }
    const float nA0 = pn0, nA1 = pn1;    // valid in all lanes

    // ---- Warp-local label dtype sniff (no smem flag, no barrier).
    // int64 LE labels (0..15) have all-zero odd 32-bit words; words [0..255]
    // are in-bounds for both layouts.
    unsigned any = 0;
#pragma unroll
    for (int k = 0; k < 4; ++k)
        any |= (unsigned)lab32[2 * (l + 32 * k) + 1];
    const bool is64 = (__ballot_sync(FULL, any != 0) == 0);
    const int labT  = is64 ? lab32[2 * t]  : lab32[t];
    const int labI0 = is64 ? lab32[2 * i0] : lab32[i0];
    const int labI1 = is64 ? lab32[2 * i1] : lab32[i1];

    __syncwarp();   // own warp's rows + anchor slot visible; no block barrier

    // ---- Phase 1 (packed f32x2): own row + warp-private anchor broadcasts.
    const ulonglong2* rowp = reinterpret_cast<const ulonglong2*>(sE + (t << 5));
    const ulonglong2* rA   = reinterpret_cast<const ulonglong2*>(sA);
    const ulonglong2* rB   = reinterpret_cast<const ulonglong2*>(sA + 32);
    ull d0x = 0, d0y = 0, d1x = 0, d1y = 0, nx = 0, ny = 0;
#pragma unroll 8
    for (int c = 0; c < 32; ++c) {
        ulonglong2 bv = rowp[(c + t) & 31];   // conflict-free (swizzle)
        ulonglong2 a0 = rA[c];                // uniform -> broadcast
        ulonglong2 a1 = rB[c];
        FMA2(d0x, bv.x, a0.x);  FMA2(d0y, bv.y, a0.y);
        FMA2(d1x, bv.x, a1.x);  FMA2(d1y, bv.y, a1.y);
        FMA2(nx,  bv.x, bv.x);  FMA2(ny,  bv.y, bv.y);
    }
    const float dot0 = unpack_add(d0x) + unpack_add(d0y);
    const float dot1 = unpack_add(d1x) + unpack_add(d1y);
    const float nt   = unpack_add(nx)  + unpack_add(ny);

    // ---- Phase 2: distances, masks, per-warp counts (no norm exchange).
    const float D0 = sqrtf(fmaxf(nA0 + nt - 2.f * dot0, 1e-4f));
    const float D1 = sqrtf(fmaxf(nA1 + nt - 2.f * dot1, 1e-4f));
    const bool p0 = (labT == labI0) && (t != i0);
    const bool p1 = (labT == labI1) && (t != i1);
    Dmat[t]     = D0;  Dmat[N + t] = D1;
    // negatives include t==i (reference's (1-pos) keeps diagonal; d_ii=0.01)
    negd[t]     = p0 ? -FLT_MAX : D0;
    negd[N + t] = p1 ? -FLT_MAX : D1;
    const unsigned bal0 = __ballot_sync(FULL, p0);
    const unsigned bal1 = __ballot_sync(FULL, p1);
    if (l == 0) { cnts[w] = __popc(bal0); cnts[8 + w] = __popc(bal1); }
    __syncthreads();   // S1: Dmat/negd/cnts ready (first block barrier)

    // ---- In-warp redundant prefix scan of the 16 counts (no extra barrier).
    int x = (l < 16) ? cnts[l] : 0;
    const int v0 = x;
#pragma unroll
    for (int d = 1; d < 16; d <<= 1) {
        int y = __shfl_up_sync(FULL, x, d);
        if (l >= d) x += y;
    }
    const int exc = x - v0;
    const int npair = __shfl_sync(FULL, x, 15);
    const int off0 = __shfl_sync(FULL, exc, w);
    const int off1 = __shfl_sync(FULL, exc, 8 + w);
    const unsigned lm = (1u << l) - 1u;
    if (p0) pairs[off0 + __popc(bal0 & lm)] = (unsigned short)t;
    if (p1) pairs[off1 + __popc(bal1 & lm)] = (unsigned short)(256 | t);
    __syncthreads();   // S2: pairs ready

    // ---- Phase 3: one warp per pair, 2 pairs in flight (chains overlap).
    float lsum = 0.f;
    for (int p = w; p < npair; p += 16) {
        const int pB = p + 8;
        const bool hasB = (pB < npair);
        const unsigned prA = pairs[p];
        const unsigned prB = pairs[hasB ? pB : p];
        const int rA_ = prA >> 8, kA = prA & 255;
        const int rB_ = prB >> 8, kB = prB & 255;
        const float DA = Dmat[rA_ * N + kA];
        const float DB = Dmat[rB_ * N + kB];
        const float* ndA = negd + rA_ * N;
        const float* ndB = negd + rB_ * N;
        float mxA = -FLT_MAX, mnA = FLT_MAX;
        float mxB = -FLT_MAX, mnB = FLT_MAX;
#pragma unroll
        for (int u = 0; u < 8; ++u) {
            float vA = ndA[u * 32 + l];
            float vB = ndB[u * 32 + l];
            mxA = fmaxf(mxA, vA);
            mnA = fminf(mnA, vA > DA ? vA : FLT_MAX);
            mxB = fmaxf(mxB, vB);
            mnB = fminf(mnB, vB > DB ? vB : FLT_MAX);
        }
#pragma unroll
        for (int s = 16; s > 0; s >>= 1) {   // four chains overlap
            mxA = fmaxf(mxA, __shfl_down_sync(FULL, mxA, s));
            mnA = fminf(mnA, __shfl_down_sync(FULL, mnA, s));
            mxB = fmaxf(mxB, __shfl_down_sync(FULL, mxB, s));
            mnB = fminf(mnB, __shfl_down_sync(FULL, mnB, s));
        }
        if (l == 0) {
            // semi-hard if strictly-farther negative exists, else easiest neg
            float sA_ = (mnA < FLT_MAX) ? (DA - mnA) : (DA - mxA);
            lsum += fmaxf(sA_ + 1.0f, 0.f);   // relu(semi + MARGIN)
            if (hasB) {
                float sB_ = (mnB < FLT_MAX) ? (DB - mnB) : (DB - mxB);
                lsum += fmaxf(sB_ + 1.0f, 0.f);
            }
        }
    }
    if (l == 0) wsum[w] = lsum;
    __syncthreads();   // S3 (last barrier)

    // ---- Ticket + finisher: warp 0 only, no fence, no more barriers.
    if (w == 0) {
        int last = 0;
        if (l == 0) {
            float S = 0.f;
#pragma unroll
            for (int k = 0; k < 8; ++k) S += wsum[k];
            g_part[b] = make_float2(S, (float)npair);
            unsigned tk, one = 1u;
            asm volatile("atom.acq_rel.gpu.global.add.u32 %0, [%1], %2;"
                         : "=r"(tk) : "l"(&g_ticket), "r"(one) : "memory");
            last = (tk == NBLK - 1);
            if (last) g_ticket = 0;   // all increments done; replay-safe
        }
        last = __shfl_sync(FULL, last, 0);
        if (last) {
            float S = 0.f, C = 0.f;
#pragma unroll
            for (int u = 0; u < 4; ++u) {
                float2 p = __ldcg(&g_part[l + 32 * u]);   // L2-direct
                S += p.x; C += p.y;
            }
#pragma unroll
            for (int s = 16; s > 0; s >>= 1) {
                S += __shfl_down_sync(FULL, S, s);
                C += __shfl_down_sync(FULL, C, s);
            }
            if (l == 0) out[0] = S / C;
        }
    }
}

extern "C" void kernel_launch(void* const* d_in, const int* in_sizes, int n_in,
                              void* d_out, int out_size) {
    const float* emb  = (const float*)d_in[0];
    const int*   labs = (const int*)d_in[1];
    float* out = (float*)d_out;
    // 8192 float4 (E) + 512 float4 (anchor slots) = 139264 B dynamic smem
    cudaFuncSetAttribute(triplet_fused,
                         cudaFuncAttributeMaxDynamicSharedMemorySize, 139264);
    triplet_fused<<<NBLK, 256, 139264>>>(emb, labs, out);
}